// round 14
// baseline (speedup 1.0000x reference)
#include <cuda_runtime.h>
#include <cuda_fp16.h>
#include <cstdint>

// ---------------------------------------------------------------------------
// Problem dims
// ---------------------------------------------------------------------------
#define I_DIM 4096   // K
#define O_DIM 4096   // N
#define M_DIM 8192   // B*S
#define R_DIM 4

// GEMM tiling: 128x128x64 CTA tile, 8 warps = 4(m) x 2(n), warp tile 32x64,
// 3-stage pipeline, 2 independent CTAs/SM. Mainloop sync via per-stage
// mbarrier full/empty pairs (1-kt-lagged) instead of per-kt __syncthreads.
#define BM 128
#define BN 128
#define BK 64
#define KITERS (I_DIM / BK)      // 64
#define STAGES 3

// SMEM: [0,48) mbarriers (full0..2 @0,8,16; empty0..2 @24,32,40), stages @1024
#define CTRL 1024
#define SA 0
#define SB 16384
#define STAGE_B 32768
#define SMEM_DYN (CTRL + STAGES * STAGE_B)   // 99328 B -> 2 CTAs/SM
// 128-byte rows -> natural SW128 swizzle: chunk ^= (row & 7)

// ---------------------------------------------------------------------------
// Static scratch (allocation-free per harness rules)
// ---------------------------------------------------------------------------
__device__ __align__(256) __half g_x16[(size_t)M_DIM * I_DIM];   // 64 MB
__device__ __align__(256) __half g_w16[(size_t)O_DIM * I_DIM];   // 32 MB

// ---------------------------------------------------------------------------
// PTX helpers (sm_80-class: cp.async, mbarrier, ldmatrix, mma.sync)
// ---------------------------------------------------------------------------
__device__ __forceinline__ uint32_t smem_u32(const void* p) {
    uint32_t a;
    asm("{ .reg .u64 t; cvta.to.shared.u64 t, %1; cvt.u32.u64 %0, t; }"
        : "=r"(a) : "l"(p));
    return a;
}

#define CP_A16(dst, src) \
    asm volatile("cp.async.cg.shared.global [%0], [%1], 16;" \
                 :: "r"(dst), "l"(src) : "memory")

// .noinc is LOAD-BEARING: the plain form increments the pending count before
// the async arrive (net zero -> barrier never trips -> R13's deadlock).
// With .noinc each thread contributes exactly one arrival (when its prior
// cp.asyncs complete) against the init count of 256.
#define CPA_MB_ARRIVE(mbar) \
    asm volatile("cp.async.mbarrier.arrive.noinc.shared.b64 [%0];" \
                 :: "r"(mbar) : "memory")

#define MBARRIER_INIT(addr, cnt) \
    asm volatile("mbarrier.init.shared.b64 [%0], %1;" :: "r"(addr), "r"(cnt) : "memory")

#define MBARRIER_ARRIVE(addr) \
    asm volatile("{\n\t.reg .b64 st;\n\tmbarrier.arrive.shared.b64 st, [%0];\n\t}" \
                 :: "r"(addr) : "memory")

#define MBAR_WAIT(addr, parity) do {                                          \
    uint32_t _m = (addr), _p = (parity), _d;                                  \
    asm volatile("{\n\t.reg .pred p;\n\t"                                     \
        "mbarrier.try_wait.parity.acquire.cta.shared::cta.b64 p, [%1], %2;\n\t" \
        "selp.b32 %0, 1, 0, p;\n\t}" : "=r"(_d) : "r"(_m), "r"(_p) : "memory"); \
    if (!_d) {                                                                \
        asm volatile("{\n\t.reg .pred P1;\n\t"                                \
            "WL_%=:\n\t"                                                      \
            "mbarrier.try_wait.parity.acquire.cta.shared::cta.b64 P1, [%0], %1;\n\t" \
            "@P1 bra.uni WD_%=;\n\t"                                          \
            "bra.uni WL_%=;\n\t"                                              \
            "WD_%=:\n\t}" :: "r"(_m), "r"(_p) : "memory");                    \
    }                                                                         \
} while (0)

__device__ __forceinline__ void ldsm4(uint32_t (&r)[4], uint32_t addr) {
    asm volatile("ldmatrix.sync.aligned.m8n8.x4.shared.b16 {%0,%1,%2,%3}, [%4];"
                 : "=r"(r[0]), "=r"(r[1]), "=r"(r[2]), "=r"(r[3]) : "r"(addr));
}

__device__ __forceinline__ void mma16816(float* d, const uint32_t* a, const uint32_t* b) {
    asm volatile(
        "mma.sync.aligned.m16n8k16.row.col.f32.f16.f16.f32 "
        "{%0,%1,%2,%3}, {%4,%5,%6,%7}, {%8,%9}, {%0,%1,%2,%3};"
        : "+f"(d[0]), "+f"(d[1]), "+f"(d[2]), "+f"(d[3])
        : "r"(a[0]), "r"(a[1]), "r"(a[2]), "r"(a[3]), "r"(b[0]), "r"(b[1]));
}

// streaming (evict-first) store: keeps C writes from thrashing x16/w16 in L2
__device__ __forceinline__ void stg_cs_f2(float* p, float2 v) {
    asm volatile("st.global.cs.v2.f32 [%0], {%1, %2};"
                 :: "l"(p), "f"(v.x), "f"(v.y) : "memory");
}

// ---------------------------------------------------------------------------
// Kernel 1: x -> fp16 (rel rounding ~2^-11; contributes ~1.3e-4 at output)
// ---------------------------------------------------------------------------
__global__ __launch_bounds__(256) void convert_x_kernel(const float* __restrict__ x) {
    const size_t i4 = ((size_t)blockIdx.x * 256 + threadIdx.x) * 4;
    const float4 v = *(const float4*)(x + i4);
    unsigned short h[4];
    h[0] = __half_as_ushort(__float2half_rn(v.x));
    h[1] = __half_as_ushort(__float2half_rn(v.y));
    h[2] = __half_as_ushort(__float2half_rn(v.z));
    h[3] = __half_as_ushort(__float2half_rn(v.w));
    uint2 hv;
    hv.x = (uint32_t)h[0] | ((uint32_t)h[1] << 16);
    hv.y = (uint32_t)h[2] | ((uint32_t)h[3] << 16);
    *(uint2*)(g_x16 + i4) = hv;
}

// ---------------------------------------------------------------------------
// Kernel 2: fused weight reconstruction -> fp16 (EXACT: |w_int| <= 255 needs
// 8 mantissa bits < fp16's 11; shift only moves the exponent).
// ---------------------------------------------------------------------------
__global__ __launch_bounds__(256) void weight_f16_kernel(
    const float* __restrict__ owr, const float* __restrict__ delta,
    const float* __restrict__ zp,  const float* __restrict__ aux,
    const float* __restrict__ loraA, const float* __restrict__ loraB)
{
    const int o  = blockIdx.y;
    const int i0 = (blockIdx.x * 256 + threadIdx.x) * 4;

    const float d  = delta[o];
    const float z  = zp[o];
    const float b0 = loraB[o * R_DIM + 0];
    const float b1 = loraB[o * R_DIM + 1];
    const float b2 = loraB[o * R_DIM + 2];
    const float b3 = loraB[o * R_DIM + 3];

    const size_t base = (size_t)o * I_DIM + i0;
    const float4 w4 = *(const float4*)(owr + base);
    const float4 x4 = *(const float4*)(aux + base);
    const float4 a0 = *(const float4*)(loraA + 0 * I_DIM + i0);
    const float4 a1 = *(const float4*)(loraA + 1 * I_DIM + i0);
    const float4 a2 = *(const float4*)(loraA + 2 * I_DIM + i0);
    const float4 a3 = *(const float4*)(loraA + 3 * I_DIM + i0);

    const float wv[4] = {w4.x, w4.y, w4.z, w4.w};
    const float av[4] = {x4.x, x4.y, x4.z, x4.w};
    const float A0[4] = {a0.x, a0.y, a0.z, a0.w};
    const float A1[4] = {a1.x, a1.y, a1.z, a1.w};
    const float A2[4] = {a2.x, a2.y, a2.z, a2.w};
    const float A3[4] = {a3.x, a3.y, a3.z, a3.w};

    unsigned short out[4];
#pragma unroll
    for (int j = 0; j < 4; j++) {
        const float w_int = wv[j] - z;
        const float denom = (w_int == 0.0f) ? 1.0f : w_int;
        float ba = b0 * A0[j];
        ba = fmaf(b1, A1[j], ba);
        ba = fmaf(b2, A2[j], ba);
        ba = fmaf(b3, A3[j], ba);
        const float wu = d + (av[j] + ba) / denom;
        const float s  = (wu > 0.0f) ? 1.0f : ((wu < 0.0f) ? -1.0f : 0.0f);
        const float shift = rintf(log2f(fabsf(wu) + 1e-16f));
        const float w = s * exp2f(shift) * w_int;   // exactly fp16-representable
        out[j] = __half_as_ushort(__float2half_rn(w));
    }
    uint2 pv;
    pv.x = (uint32_t)out[0] | ((uint32_t)out[1] << 16);
    pv.y = (uint32_t)out[2] | ((uint32_t)out[3] << 16);
    *(uint2*)(g_w16 + base) = pv;
}

// ---------------------------------------------------------------------------
// Kernel 3: mma.sync fp16 GEMM with mbarrier-phased pipeline (no per-kt
// __syncthreads: full[s] trips via cp.async.mbarrier.arrive.noinc when all
// 256 threads' loads land; empty[s] trips when all threads finished reading —
// a 1-kt-lagged dependency instead of a same-kt rendezvous).
// ---------------------------------------------------------------------------
__global__ __launch_bounds__(256, 2) void gemm_mma_kernel(
    const float* __restrict__ bias, float* __restrict__ C)
{
    extern __shared__ char smem[];
    const uint32_t sbase = smem_u32(smem);
    const uint32_t full0  = sbase + 0,  full1  = sbase + 8,  full2  = sbase + 16;
    const uint32_t empty0 = sbase + 24, empty1 = sbase + 32, empty2 = sbase + 40;
    const uint32_t s0 = sbase + CTRL, s1 = s0 + STAGE_B, s2 = s0 + 2 * STAGE_B;

    const int tid  = threadIdx.x;
    const int lane = tid & 31;
    const int wid  = tid >> 5;
    const int warp_m = wid >> 1;                 // 0..3 (32 rows each)
    const int warp_n = wid & 1;                  // 0..1 (64 cols each)
    const int bm = blockIdx.y * BM;
    const int bn = blockIdx.x * BN;

    if (tid == 0) {
        MBARRIER_INIT(full0, 256);  MBARRIER_INIT(full1, 256);  MBARRIER_INIT(full2, 256);
        MBARRIER_INIT(empty0, 256); MBARRIER_INIT(empty1, 256); MBARRIER_INIT(empty2, 256);
    }
    __syncthreads();
    // pre-complete empty2 phase 0 (all 256 threads arrive): stage2's first
    // write (prefetch of kt=2 inside body(0)) has no prior readers.
    MBARRIER_ARRIVE(empty2);

    // ---- loader: thread t -> row lr (0..31, +32 steps), 16B chunk lc (0..7)
    const int lr = tid >> 3;
    const int lc = tid & 7;
    const uint32_t so0 = (uint32_t)(lr * 128 + ((lc ^ (lr & 7)) * 16));
    const char* gA = (const char*)g_x16 + (size_t)(bm + lr) * (I_DIM * 2) + lc * 16;
    const char* gB = (const char*)g_w16 + (size_t)(bn + lr) * (I_DIM * 2) + lc * 16;
    const size_t RSTEP = (size_t)32 * (I_DIM * 2);

    auto load_stage = [&](uint32_t st, int kt) {
        const size_t ko = (size_t)kt * (BK * 2);
#pragma unroll
        for (int it = 0; it < 4; ++it) {          // 128 rows per operand
            CP_A16(st + SA + so0 + it * 4096, gA + ko + it * RSTEP);
            CP_A16(st + SB + so0 + it * 4096, gB + ko + it * RSTEP);
        }
    };

    // ---- ldmatrix lane offsets for ks=0; addr ^ (ks*32) selects k16 step ----
    uint32_t aoff[2], boff[4];
    {
        const int ar  = warp_m * 32 + (lane & 15);
        const int ach = lane >> 4;
#pragma unroll
        for (int i = 0; i < 2; ++i) {
            const int r = ar + i * 16;
            aoff[i] = (uint32_t)(r * 128 + ((ach ^ (r & 7)) * 16));
        }
        const int br  = warp_n * 64 + ((lane >> 4) << 3) + (lane & 7);
        const int bch = (lane >> 3) & 1;
#pragma unroll
        for (int j = 0; j < 4; ++j) {
            const int r = br + j * 16;
            boff[j] = (uint32_t)(r * 128 + ((bch ^ (r & 7)) * 16));
        }
    }

    float acc[2][8][4];
#pragma unroll
    for (int i = 0; i < 2; ++i)
#pragma unroll
        for (int j = 0; j < 8; ++j)
#pragma unroll
            for (int c = 0; c < 4; ++c) acc[i][j][c] = 0.0f;

    // body(kt): wait empty(kt+2) then prefetch it; wait full(kt), compute,
    // arrive empty(kt). One parity bit per 3-kt unrolled iteration.
    auto body = [&](int kt, uint32_t st_cur, uint32_t fcur, uint32_t ecur,
                    uint32_t st_nx, uint32_t fnx, uint32_t enx, uint32_t p) {
        if (kt + 2 < KITERS) {
            MBAR_WAIT(enx, p);              // stage(kt+2) readers (kt-1) done
            load_stage(st_nx, kt + 2);
            CPA_MB_ARRIVE(fnx);             // arrives when this thread's loads land
        }
        MBAR_WAIT(fcur, p);                 // all 256 threads' loads for kt landed
#pragma unroll
        for (int ks = 0; ks < 4; ++ks) {
            const uint32_t kx = ks * 32;
            uint32_t af[2][4], bf[4][4];
#pragma unroll
            for (int i = 0; i < 2; ++i)
                ldsm4(af[i], st_cur + SA + (aoff[i] ^ kx));
#pragma unroll
            for (int j = 0; j < 4; ++j)
                ldsm4(bf[j], st_cur + SB + (boff[j] ^ kx));
#pragma unroll
            for (int i = 0; i < 2; ++i)
#pragma unroll
                for (int j = 0; j < 4; ++j) {
                    mma16816(acc[i][2 * j],     af[i], &bf[j][0]);
                    mma16816(acc[i][2 * j + 1], af[i], &bf[j][2]);
                }
        }
        MBARRIER_ARRIVE(ecur);              // this thread done reading stage kt
    };

    // ---- prologue: fill stages 0 and 1 ----
    load_stage(s0, 0); CPA_MB_ARRIVE(full0);
    load_stage(s1, 1); CPA_MB_ARRIVE(full1);

    // KITERS = 64 = 21*3 + 1
    uint32_t p = 0;
#pragma unroll 1
    for (int kt = 0; kt < 63; kt += 3) {
        body(kt + 0, s0, full0, empty0, s2, full2, empty2, p);
        body(kt + 1, s1, full1, empty1, s0, full0, empty0, p);
        body(kt + 2, s2, full2, empty2, s1, full1, empty1, p);
        p ^= 1;
    }
    body(63, s0, full0, empty0, s2, full2, empty2, p);   // p = 1 = ph21 parity

    // ---- epilogue: streaming stores (evict-first; protect L2 residency) ----
#pragma unroll
    for (int i = 0; i < 2; ++i) {
        const int r0 = bm + warp_m * 32 + i * 16 + (lane >> 2);
#pragma unroll
        for (int jn = 0; jn < 8; ++jn) {
            const int col = bn + warp_n * 64 + jn * 8 + (lane & 3) * 2;
            const float2 bz = *(const float2*)(bias + col);
            stg_cs_f2(C + (size_t)r0 * O_DIM + col,
                      make_float2(acc[i][jn][0] + bz.x, acc[i][jn][1] + bz.y));
            stg_cs_f2(C + (size_t)(r0 + 8) * O_DIM + col,
                      make_float2(acc[i][jn][2] + bz.x, acc[i][jn][3] + bz.y));
        }
    }
}

// ---------------------------------------------------------------------------
// Launch
// ---------------------------------------------------------------------------
extern "C" void kernel_launch(void* const* d_in, const int* in_sizes, int n_in,
                              void* d_out, int out_size)
{
    const float* x     = (const float*)d_in[0];
    const float* owr   = (const float*)d_in[1];
    const float* delta = (const float*)d_in[2];
    const float* zp    = (const float*)d_in[3];
    const float* aux   = (const float*)d_in[4];
    const float* loraA = (const float*)d_in[5];
    const float* loraB = (const float*)d_in[6];
    const float* bias  = (const float*)d_in[7];
    float* out = (float*)d_out;

    cudaFuncSetAttribute(gemm_mma_kernel,
                         cudaFuncAttributeMaxDynamicSharedMemorySize, SMEM_DYN);

    // 1) x -> fp16
    convert_x_kernel<<<(int)(((size_t)M_DIM * I_DIM) / (256 * 4)), 256>>>(x);

    // 2) weight reconstruction -> fp16 (exact representation)
    weight_f16_kernel<<<dim3(I_DIM / 1024, O_DIM), 256>>>(owr, delta, zp, aux, loraA, loraB);

    // 3) tensor-core GEMM (fp16 mma.sync, fp32 accum, mbarrier pipeline) + bias
    gemm_mma_kernel<<<dim3(O_DIM / BN, M_DIM / BM), 256, SMEM_DYN>>>(bias, out);
}

// round 15
// speedup vs baseline: 1.0601x; 1.0601x over previous
#include <cuda_runtime.h>
#include <cuda_fp16.h>
#include <cstdint>

// ---------------------------------------------------------------------------
// Problem dims
// ---------------------------------------------------------------------------
#define I_DIM 4096   // K
#define O_DIM 4096   // N
#define M_DIM 8192   // B*S
#define R_DIM 4

// GEMM tiling: 128x128x64 CTA tile, 8 warps = 4(m) x 2(n), warp tile 32x64,
// 3-stage cp.async pipeline, 2 independent CTAs/SM. FROZEN at the R11 form:
// sync-axis probes (R9 BK=64, R13/14 mbarrier) and tile probes (R8, R10)
// all failed to beat it; regs=128 leaves no room for frag double-buffering.
#define BM 128
#define BN 128
#define BK 64
#define KITERS (I_DIM / BK)      // 64
#define STAGES 3

// SMEM stage layout: A[128][64]fp16 (16KB) | B[128][64]fp16 (16KB)
#define SA 0
#define SB 16384
#define STAGE_B 32768
#define SMEM_DYN (STAGES * STAGE_B)   // 98304 B -> 2 CTAs/SM (192KB <= 227KB)
// 128-byte rows -> natural SW128 swizzle: chunk ^= (row & 7)

// ---------------------------------------------------------------------------
// Static scratch (allocation-free per harness rules)
// ---------------------------------------------------------------------------
__device__ __align__(256) __half g_x16[(size_t)M_DIM * I_DIM];   // 64 MB
__device__ __align__(256) __half g_w16[(size_t)O_DIM * I_DIM];   // 32 MB

// ---------------------------------------------------------------------------
// PTX helpers (sm_80-class: cp.async, ldmatrix, mma.sync)
// ---------------------------------------------------------------------------
__device__ __forceinline__ uint32_t smem_u32(const void* p) {
    uint32_t a;
    asm("{ .reg .u64 t; cvta.to.shared.u64 t, %1; cvt.u32.u64 %0, t; }"
        : "=r"(a) : "l"(p));
    return a;
}

#define CP_A16(dst, src) \
    asm volatile("cp.async.cg.shared.global [%0], [%1], 16;" \
                 :: "r"(dst), "l"(src) : "memory")
#define CP_COMMIT() asm volatile("cp.async.commit_group;" ::: "memory")
#define CP_WAIT1()  asm volatile("cp.async.wait_group 1;" ::: "memory")

__device__ __forceinline__ void ldsm4(uint32_t (&r)[4], uint32_t addr) {
    asm volatile("ldmatrix.sync.aligned.m8n8.x4.shared.b16 {%0,%1,%2,%3}, [%4];"
                 : "=r"(r[0]), "=r"(r[1]), "=r"(r[2]), "=r"(r[3]) : "r"(addr));
}

__device__ __forceinline__ void mma16816(float* d, const uint32_t* a, const uint32_t* b) {
    asm volatile(
        "mma.sync.aligned.m16n8k16.row.col.f32.f16.f16.f32 "
        "{%0,%1,%2,%3}, {%4,%5,%6,%7}, {%8,%9}, {%0,%1,%2,%3};"
        : "+f"(d[0]), "+f"(d[1]), "+f"(d[2]), "+f"(d[3])
        : "r"(a[0]), "r"(a[1]), "r"(a[2]), "r"(a[3]), "r"(b[0]), "r"(b[1]));
}

// streaming (evict-first) store: keeps C writes from thrashing x16/w16 in L2
__device__ __forceinline__ void stg_cs_f2(float* p, float2 v) {
    asm volatile("st.global.cs.v2.f32 [%0], {%1, %2};"
                 :: "l"(p), "f"(v.x), "f"(v.y) : "memory");
}

// ---------------------------------------------------------------------------
// Kernel 1: x -> fp16, 16 elems/thread with 4 independent float4 loads
// batched first (MLP=4; the R14 profile showed MLP=1 latency-limited 65%).
// ---------------------------------------------------------------------------
__global__ __launch_bounds__(256) void convert_x_kernel(const float* __restrict__ x) {
    const size_t b0 = ((size_t)blockIdx.x * 256 + threadIdx.x) * 16;
    float4 v[4];
#pragma unroll
    for (int q = 0; q < 4; ++q) v[q] = *(const float4*)(x + b0 + q * 4);
#pragma unroll
    for (int q = 0; q < 4; ++q) {
        unsigned short h[4];
        h[0] = __half_as_ushort(__float2half_rn(v[q].x));
        h[1] = __half_as_ushort(__float2half_rn(v[q].y));
        h[2] = __half_as_ushort(__float2half_rn(v[q].z));
        h[3] = __half_as_ushort(__float2half_rn(v[q].w));
        uint2 hv;
        hv.x = (uint32_t)h[0] | ((uint32_t)h[1] << 16);
        hv.y = (uint32_t)h[2] | ((uint32_t)h[3] << 16);
        *(uint2*)(g_x16 + b0 + q * 4) = hv;
    }
}

// ---------------------------------------------------------------------------
// Kernel 2: weight reconstruction -> fp16, 16 elems/thread, loads batched
// per-operand for MLP. (EXACT in fp16: |w_int| <= 255 needs 8 mantissa bits
// < fp16's 11; shift only moves the exponent.)
// One block handles one full row o (256 thr x 16 = 4096 = I_DIM).
// ---------------------------------------------------------------------------
__global__ __launch_bounds__(256) void weight_f16_kernel(
    const float* __restrict__ owr, const float* __restrict__ delta,
    const float* __restrict__ zp,  const float* __restrict__ aux,
    const float* __restrict__ loraA, const float* __restrict__ loraB)
{
    const int o  = blockIdx.x;
    const int i0 = threadIdx.x * 16;

    const float d  = delta[o];
    const float z  = zp[o];
    const float b0 = loraB[o * R_DIM + 0];
    const float b1 = loraB[o * R_DIM + 1];
    const float b2 = loraB[o * R_DIM + 2];
    const float b3 = loraB[o * R_DIM + 3];

    const size_t base = (size_t)o * I_DIM + i0;

    // batched independent loads (MLP): 4 quads x (owr, aux, A0..A3)
    float4 w4[4], x4[4], a0[4], a1[4], a2[4], a3[4];
#pragma unroll
    for (int q = 0; q < 4; ++q) {
        w4[q] = *(const float4*)(owr + base + q * 4);
        x4[q] = *(const float4*)(aux + base + q * 4);
        a0[q] = *(const float4*)(loraA + 0 * I_DIM + i0 + q * 4);
        a1[q] = *(const float4*)(loraA + 1 * I_DIM + i0 + q * 4);
        a2[q] = *(const float4*)(loraA + 2 * I_DIM + i0 + q * 4);
        a3[q] = *(const float4*)(loraA + 3 * I_DIM + i0 + q * 4);
    }

#pragma unroll
    for (int q = 0; q < 4; ++q) {
        const float wv[4] = {w4[q].x, w4[q].y, w4[q].z, w4[q].w};
        const float av[4] = {x4[q].x, x4[q].y, x4[q].z, x4[q].w};
        const float A0[4] = {a0[q].x, a0[q].y, a0[q].z, a0[q].w};
        const float A1[4] = {a1[q].x, a1[q].y, a1[q].z, a1[q].w};
        const float A2[4] = {a2[q].x, a2[q].y, a2[q].z, a2[q].w};
        const float A3[4] = {a3[q].x, a3[q].y, a3[q].z, a3[q].w};

        unsigned short out[4];
#pragma unroll
        for (int j = 0; j < 4; j++) {
            const float w_int = wv[j] - z;
            const float denom = (w_int == 0.0f) ? 1.0f : w_int;
            float ba = b0 * A0[j];
            ba = fmaf(b1, A1[j], ba);
            ba = fmaf(b2, A2[j], ba);
            ba = fmaf(b3, A3[j], ba);
            const float wu = d + (av[j] + ba) / denom;
            const float s  = (wu > 0.0f) ? 1.0f : ((wu < 0.0f) ? -1.0f : 0.0f);
            const float shift = rintf(log2f(fabsf(wu) + 1e-16f));
            const float w = s * exp2f(shift) * w_int;  // exactly fp16-representable
            out[j] = __half_as_ushort(__float2half_rn(w));
        }
        uint2 pv;
        pv.x = (uint32_t)out[0] | ((uint32_t)out[1] << 16);
        pv.y = (uint32_t)out[2] | ((uint32_t)out[3] << 16);
        *(uint2*)(g_w16 + base + q * 4) = pv;
    }
}

// ---------------------------------------------------------------------------
// Kernel 3: mma.sync fp16 GEMM.  C = x16[M,K] * W16[N,K]^T + bias
//   UNCHANGED R11 winner: streaming .cs epilogue, x3-unrolled kt loop with
//   compile-time stage offsets, SW128 chunk^=row&7 swizzle, occ 2.
// ---------------------------------------------------------------------------
__global__ __launch_bounds__(256, 2) void gemm_mma_kernel(
    const float* __restrict__ bias, float* __restrict__ C)
{
    extern __shared__ char smem[];
    const uint32_t sbase = smem_u32(smem);
    const int tid  = threadIdx.x;
    const int lane = tid & 31;
    const int wid  = tid >> 5;
    const int warp_m = wid >> 1;                 // 0..3 (32 rows each)
    const int warp_n = wid & 1;                  // 0..1 (64 cols each)
    const int bm = blockIdx.y * BM;
    const int bn = blockIdx.x * BN;

    // ---- loader: thread t -> row lr (0..31, +32 steps), 16B chunk lc (0..7)
    const int lr = tid >> 3;
    const int lc = tid & 7;
    const uint32_t so0 = (uint32_t)(lr * 128 + ((lc ^ (lr & 7)) * 16));
    const char* gA = (const char*)g_x16 + (size_t)(bm + lr) * (I_DIM * 2) + lc * 16;
    const char* gB = (const char*)g_w16 + (size_t)(bn + lr) * (I_DIM * 2) + lc * 16;
    const size_t RSTEP = (size_t)32 * (I_DIM * 2);

    auto load_stage = [&](uint32_t st, int kt) {
        const size_t ko = (size_t)kt * (BK * 2);
#pragma unroll
        for (int it = 0; it < 4; ++it) {          // 128 rows per operand
            CP_A16(st + SA + so0 + it * 4096, gA + ko + it * RSTEP);
            CP_A16(st + SB + so0 + it * 4096, gB + ko + it * RSTEP);
        }
    };

    // ---- ldmatrix lane offsets for ks=0; addr ^ (ks*32) selects k16 step ----
    uint32_t aoff[2], boff[4];
    {
        const int ar  = warp_m * 32 + (lane & 15);
        const int ach = lane >> 4;
#pragma unroll
        for (int i = 0; i < 2; ++i) {
            const int r = ar + i * 16;
            aoff[i] = (uint32_t)(r * 128 + ((ach ^ (r & 7)) * 16));
        }
        const int br  = warp_n * 64 + ((lane >> 4) << 3) + (lane & 7);
        const int bch = (lane >> 3) & 1;
#pragma unroll
        for (int j = 0; j < 4; ++j) {
            const int r = br + j * 16;
            boff[j] = (uint32_t)(r * 128 + ((bch ^ (r & 7)) * 16));
        }
    }

    float acc[2][8][4];
#pragma unroll
    for (int i = 0; i < 2; ++i)
#pragma unroll
        for (int j = 0; j < 8; ++j)
#pragma unroll
            for (int c = 0; c < 4; ++c) acc[i][j][c] = 0.0f;

    auto body = [&](int kt, uint32_t st_cur, uint32_t st_next) {
        CP_WAIT1();                  // stage kt resident
        __syncthreads();             // stage being overwritten is fully read
        if (kt + 2 < KITERS) load_stage(st_next, kt + 2);
        CP_COMMIT();
#pragma unroll
        for (int ks = 0; ks < 4; ++ks) {
            const uint32_t kx = ks * 32;
            uint32_t af[2][4], bf[4][4];
#pragma unroll
            for (int i = 0; i < 2; ++i)
                ldsm4(af[i], st_cur + SA + (aoff[i] ^ kx));
#pragma unroll
            for (int j = 0; j < 4; ++j)
                ldsm4(bf[j], st_cur + SB + (boff[j] ^ kx));
#pragma unroll
            for (int i = 0; i < 2; ++i)
#pragma unroll
                for (int j = 0; j < 4; ++j) {
                    mma16816(acc[i][2 * j],     af[i], &bf[j][0]);
                    mma16816(acc[i][2 * j + 1], af[i], &bf[j][2]);
                }
        }
    };

    const uint32_t s0 = sbase, s1 = sbase + STAGE_B, s2 = sbase + 2 * STAGE_B;

    // ---- prologue: fill 2 stages ----
    load_stage(s0, 0); CP_COMMIT();
    load_stage(s1, 1); CP_COMMIT();

    // KITERS = 64 = 21*3 + 1: unrolled groups of 3, then the final kt (stage 0)
#pragma unroll 1
    for (int kt = 0; kt < 63; kt += 3) {
        body(kt + 0, s0, s2);
        body(kt + 1, s1, s0);
        body(kt + 2, s2, s1);
    }
    body(63, s0, s2);

    // ---- epilogue: streaming stores (evict-first; protect L2 residency) ----
#pragma unroll
    for (int i = 0; i < 2; ++i) {
        const int r0 = bm + warp_m * 32 + i * 16 + (lane >> 2);
#pragma unroll
        for (int jn = 0; jn < 8; ++jn) {
            const int col = bn + warp_n * 64 + jn * 8 + (lane & 3) * 2;
            const float2 bz = *(const float2*)(bias + col);
            stg_cs_f2(C + (size_t)r0 * O_DIM + col,
                      make_float2(acc[i][jn][0] + bz.x, acc[i][jn][1] + bz.y));
            stg_cs_f2(C + (size_t)(r0 + 8) * O_DIM + col,
                      make_float2(acc[i][jn][2] + bz.x, acc[i][jn][3] + bz.y));
        }
    }
}

// ---------------------------------------------------------------------------
// Launch
// ---------------------------------------------------------------------------
extern "C" void kernel_launch(void* const* d_in, const int* in_sizes, int n_in,
                              void* d_out, int out_size)
{
    const float* x     = (const float*)d_in[0];
    const float* owr   = (const float*)d_in[1];
    const float* delta = (const float*)d_in[2];
    const float* zp    = (const float*)d_in[3];
    const float* aux   = (const float*)d_in[4];
    const float* loraA = (const float*)d_in[5];
    const float* loraB = (const float*)d_in[6];
    const float* bias  = (const float*)d_in[7];
    float* out = (float*)d_out;

    cudaFuncSetAttribute(gemm_mma_kernel,
                         cudaFuncAttributeMaxDynamicSharedMemorySize, SMEM_DYN);

    // 1) x -> fp16 (16 elems/thread, MLP=4): 33.5M/(256*16) = 8192 blocks
    convert_x_kernel<<<(int)(((size_t)M_DIM * I_DIM) / (256 * 16)), 256>>>(x);

    // 2) weight reconstruction -> fp16: one block per output row
    weight_f16_kernel<<<O_DIM, 256>>>(owr, delta, zp, aux, loraA, loraB);

    // 3) tensor-core GEMM (fp16 mma.sync, fp32 accum) + bias
    gemm_mma_kernel<<<dim3(O_DIM / BN, M_DIM / BM), 256, SMEM_DYN>>>(bias, out);
}

// round 16
// speedup vs baseline: 1.0910x; 1.0291x over previous
#include <cuda_runtime.h>
#include <cuda_fp16.h>
#include <cstdint>

// ---------------------------------------------------------------------------
// Problem dims
// ---------------------------------------------------------------------------
#define I_DIM 4096   // K
#define O_DIM 4096   // N
#define M_DIM 8192   // B*S
#define R_DIM 4

// GEMM tiling: 128x128x64 CTA tile, 8 warps = 4(m) x 2(n), warp tile 32x64,
// 3-stage cp.async pipeline, 2 independent CTAs/SM. FROZEN at the R11 form
// (best measured: GEMM ~608us wall, tensor pipe 81%).
#define BM 128
#define BN 128
#define BK 64
#define KITERS (I_DIM / BK)      // 64
#define STAGES 3

// SMEM stage layout: A[128][64]fp16 (16KB) | B[128][64]fp16 (16KB)
#define SA 0
#define SB 16384
#define STAGE_B 32768
#define SMEM_DYN (STAGES * STAGE_B)   // 98304 B -> 2 CTAs/SM (192KB <= 227KB)
// 128-byte rows -> natural SW128 swizzle: chunk ^= (row & 7)

// ---------------------------------------------------------------------------
// Static scratch (allocation-free per harness rules)
// ---------------------------------------------------------------------------
__device__ __align__(256) __half g_x16[(size_t)M_DIM * I_DIM];   // 64 MB
__device__ __align__(256) __half g_w16[(size_t)O_DIM * I_DIM];   // 32 MB

// ---------------------------------------------------------------------------
// PTX helpers (sm_80-class: cp.async, ldmatrix, mma.sync)
// ---------------------------------------------------------------------------
__device__ __forceinline__ uint32_t smem_u32(const void* p) {
    uint32_t a;
    asm("{ .reg .u64 t; cvta.to.shared.u64 t, %1; cvt.u32.u64 %0, t; }"
        : "=r"(a) : "l"(p));
    return a;
}

#define CP_A16(dst, src) \
    asm volatile("cp.async.cg.shared.global [%0], [%1], 16;" \
                 :: "r"(dst), "l"(src) : "memory")
#define CP_COMMIT() asm volatile("cp.async.commit_group;" ::: "memory")
#define CP_WAIT1()  asm volatile("cp.async.wait_group 1;" ::: "memory")

__device__ __forceinline__ void ldsm4(uint32_t (&r)[4], uint32_t addr) {
    asm volatile("ldmatrix.sync.aligned.m8n8.x4.shared.b16 {%0,%1,%2,%3}, [%4];"
                 : "=r"(r[0]), "=r"(r[1]), "=r"(r[2]), "=r"(r[3]) : "r"(addr));
}

__device__ __forceinline__ void mma16816(float* d, const uint32_t* a, const uint32_t* b) {
    asm volatile(
        "mma.sync.aligned.m16n8k16.row.col.f32.f16.f16.f32 "
        "{%0,%1,%2,%3}, {%4,%5,%6,%7}, {%8,%9}, {%0,%1,%2,%3};"
        : "+f"(d[0]), "+f"(d[1]), "+f"(d[2]), "+f"(d[3])
        : "r"(a[0]), "r"(a[1]), "r"(a[2]), "r"(a[3]), "r"(b[0]), "r"(b[1]));
}

// streaming (evict-first) store: keeps C writes from thrashing x16/w16 in L2
__device__ __forceinline__ void stg_cs_f2(float* p, float2 v) {
    asm volatile("st.global.cs.v2.f32 [%0], {%1, %2};"
                 :: "l"(p), "f"(v.x), "f"(v.y) : "memory");
}

// ---------------------------------------------------------------------------
// Kernel 1: x -> fp16, 16 elems/thread, 4 independent float4 loads batched
// first (MLP=4). Measured 26.9us @ DRAM 75.7% in R15.
// ---------------------------------------------------------------------------
__global__ __launch_bounds__(256) void convert_x_kernel(const float* __restrict__ x) {
    const size_t b0 = ((size_t)blockIdx.x * 256 + threadIdx.x) * 16;
    float4 v[4];
#pragma unroll
    for (int q = 0; q < 4; ++q) v[q] = *(const float4*)(x + b0 + q * 4);
#pragma unroll
    for (int q = 0; q < 4; ++q) {
        unsigned short h[4];
        h[0] = __half_as_ushort(__float2half_rn(v[q].x));
        h[1] = __half_as_ushort(__float2half_rn(v[q].y));
        h[2] = __half_as_ushort(__float2half_rn(v[q].z));
        h[3] = __half_as_ushort(__float2half_rn(v[q].w));
        uint2 hv;
        hv.x = (uint32_t)h[0] | ((uint32_t)h[1] << 16);
        hv.y = (uint32_t)h[2] | ((uint32_t)h[3] << 16);
        *(uint2*)(g_x16 + b0 + q * 4) = hv;
    }
}

// ---------------------------------------------------------------------------
// Kernel 2: weight reconstruction -> fp16 — R11 form (4 elems/thread; the six
// float4 loads below are mutually independent = natural MLP 6, low regs).
// EXACT in fp16: |w_int| <= 255 needs 8 mantissa bits < fp16's 11; the
// 2^shift factor only moves the exponent.
// ---------------------------------------------------------------------------
__global__ __launch_bounds__(256) void weight_f16_kernel(
    const float* __restrict__ owr, const float* __restrict__ delta,
    const float* __restrict__ zp,  const float* __restrict__ aux,
    const float* __restrict__ loraA, const float* __restrict__ loraB)
{
    const int o  = blockIdx.y;
    const int i0 = (blockIdx.x * 256 + threadIdx.x) * 4;

    const float d  = delta[o];
    const float z  = zp[o];
    const float b0 = loraB[o * R_DIM + 0];
    const float b1 = loraB[o * R_DIM + 1];
    const float b2 = loraB[o * R_DIM + 2];
    const float b3 = loraB[o * R_DIM + 3];

    const size_t base = (size_t)o * I_DIM + i0;
    const float4 w4 = *(const float4*)(owr + base);
    const float4 x4 = *(const float4*)(aux + base);
    const float4 a0 = *(const float4*)(loraA + 0 * I_DIM + i0);
    const float4 a1 = *(const float4*)(loraA + 1 * I_DIM + i0);
    const float4 a2 = *(const float4*)(loraA + 2 * I_DIM + i0);
    const float4 a3 = *(const float4*)(loraA + 3 * I_DIM + i0);

    const float wv[4] = {w4.x, w4.y, w4.z, w4.w};
    const float av[4] = {x4.x, x4.y, x4.z, x4.w};
    const float A0[4] = {a0.x, a0.y, a0.z, a0.w};
    const float A1[4] = {a1.x, a1.y, a1.z, a1.w};
    const float A2[4] = {a2.x, a2.y, a2.z, a2.w};
    const float A3[4] = {a3.x, a3.y, a3.z, a3.w};

    unsigned short out[4];
#pragma unroll
    for (int j = 0; j < 4; j++) {
        const float w_int = wv[j] - z;
        const float denom = (w_int == 0.0f) ? 1.0f : w_int;
        float ba = b0 * A0[j];
        ba = fmaf(b1, A1[j], ba);
        ba = fmaf(b2, A2[j], ba);
        ba = fmaf(b3, A3[j], ba);
        const float wu = d + (av[j] + ba) / denom;
        const float s  = (wu > 0.0f) ? 1.0f : ((wu < 0.0f) ? -1.0f : 0.0f);
        const float shift = rintf(log2f(fabsf(wu) + 1e-16f));
        const float w = s * exp2f(shift) * w_int;   // exactly fp16-representable
        out[j] = __half_as_ushort(__float2half_rn(w));
    }
    uint2 pv;
    pv.x = (uint32_t)out[0] | ((uint32_t)out[1] << 16);
    pv.y = (uint32_t)out[2] | ((uint32_t)out[3] << 16);
    *(uint2*)(g_w16 + base) = pv;
}

// ---------------------------------------------------------------------------
// Kernel 3: mma.sync fp16 GEMM.  C = x16[M,K] * W16[N,K]^T + bias
//   UNCHANGED R11 winner: streaming .cs epilogue, x3-unrolled kt loop with
//   compile-time stage offsets, SW128 chunk^=row&7 swizzle, occ 2.
// ---------------------------------------------------------------------------
__global__ __launch_bounds__(256, 2) void gemm_mma_kernel(
    const float* __restrict__ bias, float* __restrict__ C)
{
    extern __shared__ char smem[];
    const uint32_t sbase = smem_u32(smem);
    const int tid  = threadIdx.x;
    const int lane = tid & 31;
    const int wid  = tid >> 5;
    const int warp_m = wid >> 1;                 // 0..3 (32 rows each)
    const int warp_n = wid & 1;                  // 0..1 (64 cols each)
    const int bm = blockIdx.y * BM;
    const int bn = blockIdx.x * BN;

    // ---- loader: thread t -> row lr (0..31, +32 steps), 16B chunk lc (0..7)
    const int lr = tid >> 3;
    const int lc = tid & 7;
    const uint32_t so0 = (uint32_t)(lr * 128 + ((lc ^ (lr & 7)) * 16));
    const char* gA = (const char*)g_x16 + (size_t)(bm + lr) * (I_DIM * 2) + lc * 16;
    const char* gB = (const char*)g_w16 + (size_t)(bn + lr) * (I_DIM * 2) + lc * 16;
    const size_t RSTEP = (size_t)32 * (I_DIM * 2);

    auto load_stage = [&](uint32_t st, int kt) {
        const size_t ko = (size_t)kt * (BK * 2);
#pragma unroll
        for (int it = 0; it < 4; ++it) {          // 128 rows per operand
            CP_A16(st + SA + so0 + it * 4096, gA + ko + it * RSTEP);
            CP_A16(st + SB + so0 + it * 4096, gB + ko + it * RSTEP);
        }
    };

    // ---- ldmatrix lane offsets for ks=0; addr ^ (ks*32) selects k16 step ----
    uint32_t aoff[2], boff[4];
    {
        const int ar  = warp_m * 32 + (lane & 15);
        const int ach = lane >> 4;
#pragma unroll
        for (int i = 0; i < 2; ++i) {
            const int r = ar + i * 16;
            aoff[i] = (uint32_t)(r * 128 + ((ach ^ (r & 7)) * 16));
        }
        const int br  = warp_n * 64 + ((lane >> 4) << 3) + (lane & 7);
        const int bch = (lane >> 3) & 1;
#pragma unroll
        for (int j = 0; j < 4; ++j) {
            const int r = br + j * 16;
            boff[j] = (uint32_t)(r * 128 + ((bch ^ (r & 7)) * 16));
        }
    }

    float acc[2][8][4];
#pragma unroll
    for (int i = 0; i < 2; ++i)
#pragma unroll
        for (int j = 0; j < 8; ++j)
#pragma unroll
            for (int c = 0; c < 4; ++c) acc[i][j][c] = 0.0f;

    auto body = [&](int kt, uint32_t st_cur, uint32_t st_next) {
        CP_WAIT1();                  // stage kt resident
        __syncthreads();             // stage being overwritten is fully read
        if (kt + 2 < KITERS) load_stage(st_next, kt + 2);
        CP_COMMIT();
#pragma unroll
        for (int ks = 0; ks < 4; ++ks) {
            const uint32_t kx = ks * 32;
            uint32_t af[2][4], bf[4][4];
#pragma unroll
            for (int i = 0; i < 2; ++i)
                ldsm4(af[i], st_cur + SA + (aoff[i] ^ kx));
#pragma unroll
            for (int j = 0; j < 4; ++j)
                ldsm4(bf[j], st_cur + SB + (boff[j] ^ kx));
#pragma unroll
            for (int i = 0; i < 2; ++i)
#pragma unroll
                for (int j = 0; j < 4; ++j) {
                    mma16816(acc[i][2 * j],     af[i], &bf[j][0]);
                    mma16816(acc[i][2 * j + 1], af[i], &bf[j][2]);
                }
        }
    };

    const uint32_t s0 = sbase, s1 = sbase + STAGE_B, s2 = sbase + 2 * STAGE_B;

    // ---- prologue: fill 2 stages ----
    load_stage(s0, 0); CP_COMMIT();
    load_stage(s1, 1); CP_COMMIT();

    // KITERS = 64 = 21*3 + 1: unrolled groups of 3, then the final kt (stage 0)
#pragma unroll 1
    for (int kt = 0; kt < 63; kt += 3) {
        body(kt + 0, s0, s2);
        body(kt + 1, s1, s0);
        body(kt + 2, s2, s1);
    }
    body(63, s0, s2);

    // ---- epilogue: streaming stores (evict-first; protect L2 residency) ----
#pragma unroll
    for (int i = 0; i < 2; ++i) {
        const int r0 = bm + warp_m * 32 + i * 16 + (lane >> 2);
#pragma unroll
        for (int jn = 0; jn < 8; ++jn) {
            const int col = bn + warp_n * 64 + jn * 8 + (lane & 3) * 2;
            const float2 bz = *(const float2*)(bias + col);
            stg_cs_f2(C + (size_t)r0 * O_DIM + col,
                      make_float2(acc[i][jn][0] + bz.x, acc[i][jn][1] + bz.y));
            stg_cs_f2(C + (size_t)(r0 + 8) * O_DIM + col,
                      make_float2(acc[i][jn][2] + bz.x, acc[i][jn][3] + bz.y));
        }
    }
}

// ---------------------------------------------------------------------------
// Launch
// ---------------------------------------------------------------------------
extern "C" void kernel_launch(void* const* d_in, const int* in_sizes, int n_in,
                              void* d_out, int out_size)
{
    const float* x     = (const float*)d_in[0];
    const float* owr   = (const float*)d_in[1];
    const float* delta = (const float*)d_in[2];
    const float* zp    = (const float*)d_in[3];
    const float* aux   = (const float*)d_in[4];
    const float* loraA = (const float*)d_in[5];
    const float* loraB = (const float*)d_in[6];
    const float* bias  = (const float*)d_in[7];
    float* out = (float*)d_out;

    cudaFuncSetAttribute(gemm_mma_kernel,
                         cudaFuncAttributeMaxDynamicSharedMemorySize, SMEM_DYN);

    // 1) x -> fp16 (16 elems/thread, MLP=4): 33.5M/(256*16) = 8192 blocks
    convert_x_kernel<<<(int)(((size_t)M_DIM * I_DIM) / (256 * 16)), 256>>>(x);

    // 2) weight reconstruction -> fp16 (R11 form: 4 elems/thread, MLP=6)
    weight_f16_kernel<<<dim3(I_DIM / 1024, O_DIM), 256>>>(owr, delta, zp, aux, loraA, loraB);

    // 3) tensor-core GEMM (fp16 mma.sync, fp32 accum) + bias
    gemm_mma_kernel<<<dim3(O_DIM / BN, M_DIM / BM), 256, SMEM_DYN>>>(bias, out);
}